// round 3
// baseline (speedup 1.0000x reference)
#include <cuda_runtime.h>
#include <cuda_bf16.h>
#include <math.h>

// Problem constants
#define B_ 2
#define L_ 2048
#define D_ 1024
#define F_ 4096
#define H_ 16
#define HD_ 64
#define M_ (B_ * L_)          // 4096 rows of tokens
#define LN_EPS 1e-6f

// ---------------------------------------------------------------------------
// Scratch (static device globals; no allocation anywhere)
// ---------------------------------------------------------------------------
__device__ float g_h[M_ * D_];        // layernorm output (reused for ln1 and ln2)
__device__ float g_qkv[M_ * 3 * D_];  // qkv projection
__device__ float g_attn[M_ * D_];     // attention output (pre-proj)
__device__ float g_x1[M_ * D_];       // residual stream after attention
__device__ float g_mid[M_ * F_];      // MLP hidden

// ---------------------------------------------------------------------------
// LayerNorm: one block per row (D=1024, 256 threads -> one float4 per thread)
// ---------------------------------------------------------------------------
__global__ __launch_bounds__(256) void layernorm_k(
    const float* __restrict__ x, const float* __restrict__ gamma,
    const float* __restrict__ beta, float* __restrict__ out)
{
    const int row = blockIdx.x;
    const int t = threadIdx.x;
    const float4 v = *(const float4*)(x + (size_t)row * D_ + t * 4);

    float s = v.x + v.y + v.z + v.w;
    float q = v.x * v.x + v.y * v.y + v.z * v.z + v.w * v.w;

    #pragma unroll
    for (int off = 16; off > 0; off >>= 1) {
        s += __shfl_down_sync(0xffffffffu, s, off);
        q += __shfl_down_sync(0xffffffffu, q, off);
    }
    __shared__ float ss[8], qq[8];
    const int wid = t >> 5, lane = t & 31;
    if (lane == 0) { ss[wid] = s; qq[wid] = q; }
    __syncthreads();
    if (t == 0) {
        float S = 0.f, Q = 0.f;
        #pragma unroll
        for (int i = 0; i < 8; i++) { S += ss[i]; Q += qq[i]; }
        ss[0] = S; qq[0] = Q;
    }
    __syncthreads();
    const float mu = ss[0] * (1.0f / D_);
    const float var = qq[0] * (1.0f / D_) - mu * mu;
    const float rstd = rsqrtf(var + LN_EPS);

    const float4 g4 = *(const float4*)(gamma + t * 4);
    const float4 b4 = *(const float4*)(beta + t * 4);
    float4 o;
    o.x = (v.x - mu) * rstd * g4.x + b4.x;
    o.y = (v.y - mu) * rstd * g4.y + b4.y;
    o.z = (v.z - mu) * rstd * g4.z + b4.z;
    o.w = (v.w - mu) * rstd * g4.w + b4.w;
    *(float4*)(out + (size_t)row * D_ + t * 4) = o;
}

// ---------------------------------------------------------------------------
// SGEMM: C[M,N] = A[M,K] @ B[K,N] (+ bias) (+ gelu) (+ residual)
// 128x128 tile, BK=8, 256 threads, 8x8 per thread.
// EPI: 0 = none, 1 = bias + residual, 2 = bias + gelu
// ---------------------------------------------------------------------------
__device__ __forceinline__ float gelu_tanh(float v) {
    const float c = 0.7978845608028654f;
    float u = c * (v + 0.044715f * v * v * v);
    return 0.5f * v * (1.0f + tanhf(u));
}

template <int EPI>
__global__ __launch_bounds__(256) void sgemm128(
    const float* __restrict__ A, const float* __restrict__ Bm,
    const float* __restrict__ bias, const float* __restrict__ res,
    float* __restrict__ C, int M, int N, int K)
{
    __shared__ float As[8][128];
    __shared__ float Bs[8][128];

    const int tid = threadIdx.x;
    const int mBase = blockIdx.y * 128;
    const int nBase = blockIdx.x * 128;

    const int aRow = tid >> 1;          // 0..127
    const int aCol = (tid & 1) * 4;     // 0 or 4
    const int bRow = tid >> 5;          // 0..7
    const int bCol = (tid & 31) * 4;    // 0..124

    const float* Aptr = A + (size_t)(mBase + aRow) * K + aCol;
    const float* Bptr = Bm + (size_t)bRow * N + nBase + bCol;

    const int tx = tid & 15;            // 0..15 -> N sub-tile
    const int ty = tid >> 4;            // 0..15 -> M sub-tile

    float acc[8][8];
    #pragma unroll
    for (int i = 0; i < 8; i++)
        #pragma unroll
        for (int j = 0; j < 8; j++) acc[i][j] = 0.f;

    for (int k0 = 0; k0 < K; k0 += 8) {
        const float4 a4 = *(const float4*)(Aptr + k0);
        const float4 b4 = *(const float4*)(Bptr + (size_t)k0 * N);
        As[aCol + 0][aRow] = a4.x;
        As[aCol + 1][aRow] = a4.y;
        As[aCol + 2][aRow] = a4.z;
        As[aCol + 3][aRow] = a4.w;
        *(float4*)&Bs[bRow][bCol] = b4;
        __syncthreads();

        #pragma unroll
        for (int k = 0; k < 8; k++) {
            const float4 a0 = *(const float4*)&As[k][ty * 8];
            const float4 a1 = *(const float4*)&As[k][ty * 8 + 4];
            const float4 b0 = *(const float4*)&Bs[k][tx * 8];
            const float4 b1 = *(const float4*)&Bs[k][tx * 8 + 4];
            const float ar[8] = {a0.x, a0.y, a0.z, a0.w, a1.x, a1.y, a1.z, a1.w};
            const float br[8] = {b0.x, b0.y, b0.z, b0.w, b1.x, b1.y, b1.z, b1.w};
            #pragma unroll
            for (int i = 0; i < 8; i++)
                #pragma unroll
                for (int j = 0; j < 8; j++)
                    acc[i][j] = fmaf(ar[i], br[j], acc[i][j]);
        }
        __syncthreads();
    }

    // Epilogue
    #pragma unroll
    for (int i = 0; i < 8; i++) {
        const int m = mBase + ty * 8 + i;
        #pragma unroll
        for (int jj = 0; jj < 8; jj += 4) {
            const int n = nBase + tx * 8 + jj;
            float4 c = make_float4(acc[i][jj], acc[i][jj + 1],
                                   acc[i][jj + 2], acc[i][jj + 3]);
            if (EPI == 1 || EPI == 2) {
                const float4 bi = *(const float4*)(bias + n);
                c.x += bi.x; c.y += bi.y; c.z += bi.z; c.w += bi.w;
            }
            if (EPI == 2) {
                c.x = gelu_tanh(c.x); c.y = gelu_tanh(c.y);
                c.z = gelu_tanh(c.z); c.w = gelu_tanh(c.w);
            }
            if (EPI == 1) {
                const float4 r = *(const float4*)(res + (size_t)m * N + n);
                c.x += r.x; c.y += r.y; c.z += r.z; c.w += r.w;
            }
            *(float4*)(C + (size_t)m * N + n) = c;
        }
    }
}

// ---------------------------------------------------------------------------
// Flash attention (fp32, online softmax). 64 queries x 64 keys per tile,
// hd=64. Grid (L/64, H, B). 256 threads: (ty=tid/16 rows, tx=tid%16 cols),
// each thread owns a 4x4 patch. Reads q/k/v directly out of g_qkv.
// ---------------------------------------------------------------------------
#define FA_STRIDE 68
#define FA_BUF (64 * FA_STRIDE)
#define FA_SMEM (4 * FA_BUF * 4)

__global__ __launch_bounds__(256) void flash_attn_k(
    const float* __restrict__ qkv, float* __restrict__ out)
{
    extern __shared__ float sm[];
    float* Qt = sm;               // [d][m] d-major, stride 68
    float* Kt = Qt + FA_BUF;      // [d][n]
    float* Vs = Kt + FA_BUF;      // [n][d]
    float* Ps = Vs + FA_BUF;      // [m][n]

    const int b = blockIdx.z;
    const int h = blockIdx.y;
    const int qb = blockIdx.x * 64;
    const int t = threadIdx.x;
    const int tm = t >> 4;        // 0..15
    const int tn = t & 15;        // 0..15

    // load Q tile (transposed into Qt[d][m])
    for (int idx = t; idx < 64 * 16; idx += 256) {
        const int m = idx >> 4;
        const int d4 = (idx & 15) * 4;
        const float4 v = *(const float4*)(
            qkv + (size_t)(b * L_ + qb + m) * (3 * D_) + h * HD_ + d4);
        Qt[(d4 + 0) * FA_STRIDE + m] = v.x;
        Qt[(d4 + 1) * FA_STRIDE + m] = v.y;
        Qt[(d4 + 2) * FA_STRIDE + m] = v.z;
        Qt[(d4 + 3) * FA_STRIDE + m] = v.w;
    }

    float mo[4] = {-INFINITY, -INFINITY, -INFINITY, -INFINITY};
    float lo[4] = {0.f, 0.f, 0.f, 0.f};
    float acc[4][4];
    #pragma unroll
    for (int i = 0; i < 4; i++)
        #pragma unroll
        for (int j = 0; j < 4; j++) acc[i][j] = 0.f;

    __syncthreads();

    for (int kb = 0; kb < L_; kb += 64) {
        // load K (transposed) and V tiles
        for (int idx = t; idx < 64 * 16; idx += 256) {
            const int n = idx >> 4;
            const int d4 = (idx & 15) * 4;
            const float* kp = qkv + (size_t)(b * L_ + kb + n) * (3 * D_)
                              + D_ + h * HD_ + d4;
            const float4 kv = *(const float4*)kp;
            Kt[(d4 + 0) * FA_STRIDE + n] = kv.x;
            Kt[(d4 + 1) * FA_STRIDE + n] = kv.y;
            Kt[(d4 + 2) * FA_STRIDE + n] = kv.z;
            Kt[(d4 + 3) * FA_STRIDE + n] = kv.w;
            *(float4*)&Vs[n * FA_STRIDE + d4] = *(const float4*)(kp + D_);
        }
        __syncthreads();

        // S = Q K^T * 0.125
        float s[4][4];
        #pragma unroll
        for (int i = 0; i < 4; i++)
            #pragma unroll
            for (int j = 0; j < 4; j++) s[i][j] = 0.f;
        #pragma unroll 4
        for (int k = 0; k < HD_; k++) {
            const float4 q4 = *(const float4*)&Qt[k * FA_STRIDE + tm * 4];
            const float4 k4 = *(const float4*)&Kt[k * FA_STRIDE + tn * 4];
            const float qr[4] = {q4.x, q4.y, q4.z, q4.w};
            const float kr[4] = {k4.x, k4.y, k4.z, k4.w};
            #pragma unroll
            for (int i = 0; i < 4; i++)
                #pragma unroll
                for (int j = 0; j < 4; j++)
                    s[i][j] = fmaf(qr[i], kr[j], s[i][j]);
        }

        // online softmax per row (16-lane reduction across tn; tn occupies
        // the low 4 lane bits so xor 1/2/4/8 stays within the row group)
        #pragma unroll
        for (int i = 0; i < 4; i++) {
            float tmax = -INFINITY;
            #pragma unroll
            for (int j = 0; j < 4; j++) {
                s[i][j] *= 0.125f;
                tmax = fmaxf(tmax, s[i][j]);
            }
            #pragma unroll
            for (int off = 8; off > 0; off >>= 1)
                tmax = fmaxf(tmax, __shfl_xor_sync(0xffffffffu, tmax, off));

            const float mnew = fmaxf(mo[i], tmax);
            const float corr = __expf(mo[i] - mnew);
            float rs = 0.f;
            #pragma unroll
            for (int j = 0; j < 4; j++) {
                const float p = __expf(s[i][j] - mnew);
                Ps[(tm * 4 + i) * FA_STRIDE + tn * 4 + j] = p;
                rs += p;
            }
            #pragma unroll
            for (int off = 8; off > 0; off >>= 1)
                rs += __shfl_xor_sync(0xffffffffu, rs, off);

            lo[i] = lo[i] * corr + rs;
            mo[i] = mnew;
            #pragma unroll
            for (int j = 0; j < 4; j++) acc[i][j] *= corr;
        }
        __syncthreads();

        // acc += P @ V
        #pragma unroll 4
        for (int kk = 0; kk < 64; kk++) {
            const float4 v4 = *(const float4*)&Vs[kk * FA_STRIDE + tn * 4];
            const float vr[4] = {v4.x, v4.y, v4.z, v4.w};
            #pragma unroll
            for (int i = 0; i < 4; i++) {
                const float p = Ps[(tm * 4 + i) * FA_STRIDE + kk];
                #pragma unroll
                for (int j = 0; j < 4; j++)
                    acc[i][j] = fmaf(p, vr[j], acc[i][j]);
            }
        }
        __syncthreads();
    }

    // write normalized output: out[b][l][h*64+d]
    #pragma unroll
    for (int i = 0; i < 4; i++) {
        const float inv = 1.0f / lo[i];
        float4 o = make_float4(acc[i][0] * inv, acc[i][1] * inv,
                               acc[i][2] * inv, acc[i][3] * inv);
        *(float4*)(out + (size_t)(b * L_ + qb + tm * 4 + i) * D_
                   + h * HD_ + tn * 4) = o;
    }
}

// ---------------------------------------------------------------------------
// Launch
// ---------------------------------------------------------------------------
extern "C" void kernel_launch(void* const* d_in, const int* in_sizes, int n_in,
                              void* d_out, int out_size)
{
    const float* x      = (const float*)d_in[0];
    const float* ln1_s  = (const float*)d_in[1];
    const float* ln1_b  = (const float*)d_in[2];
    const float* w_qkv  = (const float*)d_in[3];
    const float* w_proj = (const float*)d_in[4];
    const float* b_proj = (const float*)d_in[5];
    const float* ln2_s  = (const float*)d_in[6];
    const float* ln2_b  = (const float*)d_in[7];
    const float* w_mlp1 = (const float*)d_in[8];
    const float* b_mlp1 = (const float*)d_in[9];
    const float* w_mlp2 = (const float*)d_in[10];
    const float* b_mlp2 = (const float*)d_in[11];
    float* out = (float*)d_out;

    float *h, *qkv, *attn, *x1, *mid;
    cudaGetSymbolAddress((void**)&h, g_h);
    cudaGetSymbolAddress((void**)&qkv, g_qkv);
    cudaGetSymbolAddress((void**)&attn, g_attn);
    cudaGetSymbolAddress((void**)&x1, g_x1);
    cudaGetSymbolAddress((void**)&mid, g_mid);

    static bool attr_set = false;
    if (!attr_set) {
        cudaFuncSetAttribute(flash_attn_k,
                             cudaFuncAttributeMaxDynamicSharedMemorySize,
                             FA_SMEM);
        attr_set = true;
    }

    // 1) pre-norm 1
    layernorm_k<<<M_, 256>>>(x, ln1_s, ln1_b, h);
    // 2) qkv projection (no bias)
    sgemm128<0><<<dim3(3 * D_ / 128, M_ / 128), 256>>>(
        h, w_qkv, nullptr, nullptr, qkv, M_, 3 * D_, D_);
    // 3) attention
    flash_attn_k<<<dim3(L_ / 64, H_, B_), 256, FA_SMEM>>>(qkv, attn);
    // 4) output projection + bias + residual
    sgemm128<1><<<dim3(D_ / 128, M_ / 128), 256>>>(
        attn, w_proj, b_proj, x, x1, M_, D_, D_);
    // 5) pre-norm 2
    layernorm_k<<<M_, 256>>>(x1, ln2_s, ln2_b, h);
    // 6) MLP up + bias + gelu
    sgemm128<2><<<dim3(F_ / 128, M_ / 128), 256>>>(
        h, w_mlp1, b_mlp1, nullptr, mid, M_, F_, D_);
    // 7) MLP down + bias + residual -> final output
    sgemm128<1><<<dim3(D_ / 128, M_ / 128), 256>>>(
        mid, w_mlp2, b_mlp2, x1, out, M_, D_, F_);
}

// round 4
// speedup vs baseline: 1.0003x; 1.0003x over previous
#include <cuda_runtime.h>
#include <cuda_bf16.h>
#include <math.h>

// Problem constants
#define B_ 2
#define L_ 2048
#define D_ 1024
#define F_ 4096
#define H_ 16
#define HD_ 64
#define M_ (B_ * L_)          // 4096 rows of tokens
#define LN_EPS 1e-6f

// ---------------------------------------------------------------------------
// Scratch (static device globals; no allocation anywhere)
// ---------------------------------------------------------------------------
__device__ float g_h[M_ * D_];        // layernorm output (reused for ln1 and ln2)
__device__ float g_qkv[M_ * 3 * D_];  // qkv projection
__device__ float g_attn[M_ * D_];     // attention output (pre-proj)
__device__ float g_x1[M_ * D_];       // residual stream after attention
__device__ float g_mid[M_ * F_];      // MLP hidden

// ---------------------------------------------------------------------------
// LayerNorm: one block per row (D=1024, 256 threads -> one float4 per thread)
// ---------------------------------------------------------------------------
__global__ __launch_bounds__(256) void layernorm_k(
    const float* __restrict__ x, const float* __restrict__ gamma,
    const float* __restrict__ beta, float* __restrict__ out)
{
    const int row = blockIdx.x;
    const int t = threadIdx.x;
    const float4 v = *(const float4*)(x + (size_t)row * D_ + t * 4);

    float s = v.x + v.y + v.z + v.w;
    float q = v.x * v.x + v.y * v.y + v.z * v.z + v.w * v.w;

    #pragma unroll
    for (int off = 16; off > 0; off >>= 1) {
        s += __shfl_down_sync(0xffffffffu, s, off);
        q += __shfl_down_sync(0xffffffffu, q, off);
    }
    __shared__ float ss[8], qq[8];
    const int wid = t >> 5, lane = t & 31;
    if (lane == 0) { ss[wid] = s; qq[wid] = q; }
    __syncthreads();
    if (t == 0) {
        float S = 0.f, Q = 0.f;
        #pragma unroll
        for (int i = 0; i < 8; i++) { S += ss[i]; Q += qq[i]; }
        ss[0] = S; qq[0] = Q;
    }
    __syncthreads();
    const float mu = ss[0] * (1.0f / D_);
    const float var = qq[0] * (1.0f / D_) - mu * mu;
    const float rstd = rsqrtf(var + LN_EPS);

    const float4 g4 = *(const float4*)(gamma + t * 4);
    const float4 b4 = *(const float4*)(beta + t * 4);
    float4 o;
    o.x = (v.x - mu) * rstd * g4.x + b4.x;
    o.y = (v.y - mu) * rstd * g4.y + b4.y;
    o.z = (v.z - mu) * rstd * g4.z + b4.z;
    o.w = (v.w - mu) * rstd * g4.w + b4.w;
    *(float4*)(out + (size_t)row * D_ + t * 4) = o;
}

// ---------------------------------------------------------------------------
// SGEMM: C[M,N] = A[M,K] @ B[K,N] (+ bias) (+ gelu) (+ residual)
// 128x128 tile, BK=8, 256 threads, 8x8 per thread.
// EPI: 0 = none, 1 = bias + residual, 2 = bias + gelu
// ---------------------------------------------------------------------------
__device__ __forceinline__ float gelu_tanh(float v) {
    const float c = 0.7978845608028654f;
    float u = c * (v + 0.044715f * v * v * v);
    return 0.5f * v * (1.0f + tanhf(u));
}

template <int EPI>
__global__ __launch_bounds__(256) void sgemm128(
    const float* __restrict__ A, const float* __restrict__ Bm,
    const float* __restrict__ bias, const float* __restrict__ res,
    float* __restrict__ C, int M, int N, int K)
{
    __shared__ float As[8][128];
    __shared__ float Bs[8][128];

    const int tid = threadIdx.x;
    const int mBase = blockIdx.y * 128;
    const int nBase = blockIdx.x * 128;

    const int aRow = tid >> 1;          // 0..127
    const int aCol = (tid & 1) * 4;     // 0 or 4
    const int bRow = tid >> 5;          // 0..7
    const int bCol = (tid & 31) * 4;    // 0..124

    const float* Aptr = A + (size_t)(mBase + aRow) * K + aCol;
    const float* Bptr = Bm + (size_t)bRow * N + nBase + bCol;

    const int tx = tid & 15;            // 0..15 -> N sub-tile
    const int ty = tid >> 4;            // 0..15 -> M sub-tile

    float acc[8][8];
    #pragma unroll
    for (int i = 0; i < 8; i++)
        #pragma unroll
        for (int j = 0; j < 8; j++) acc[i][j] = 0.f;

    for (int k0 = 0; k0 < K; k0 += 8) {
        const float4 a4 = *(const float4*)(Aptr + k0);
        const float4 b4 = *(const float4*)(Bptr + (size_t)k0 * N);
        As[aCol + 0][aRow] = a4.x;
        As[aCol + 1][aRow] = a4.y;
        As[aCol + 2][aRow] = a4.z;
        As[aCol + 3][aRow] = a4.w;
        *(float4*)&Bs[bRow][bCol] = b4;
        __syncthreads();

        #pragma unroll
        for (int k = 0; k < 8; k++) {
            const float4 a0 = *(const float4*)&As[k][ty * 8];
            const float4 a1 = *(const float4*)&As[k][ty * 8 + 4];
            const float4 b0 = *(const float4*)&Bs[k][tx * 8];
            const float4 b1 = *(const float4*)&Bs[k][tx * 8 + 4];
            const float ar[8] = {a0.x, a0.y, a0.z, a0.w, a1.x, a1.y, a1.z, a1.w};
            const float br[8] = {b0.x, b0.y, b0.z, b0.w, b1.x, b1.y, b1.z, b1.w};
            #pragma unroll
            for (int i = 0; i < 8; i++)
                #pragma unroll
                for (int j = 0; j < 8; j++)
                    acc[i][j] = fmaf(ar[i], br[j], acc[i][j]);
        }
        __syncthreads();
    }

    // Epilogue
    #pragma unroll
    for (int i = 0; i < 8; i++) {
        const int m = mBase + ty * 8 + i;
        #pragma unroll
        for (int jj = 0; jj < 8; jj += 4) {
            const int n = nBase + tx * 8 + jj;
            float4 c = make_float4(acc[i][jj], acc[i][jj + 1],
                                   acc[i][jj + 2], acc[i][jj + 3]);
            if (EPI == 1 || EPI == 2) {
                const float4 bi = *(const float4*)(bias + n);
                c.x += bi.x; c.y += bi.y; c.z += bi.z; c.w += bi.w;
            }
            if (EPI == 2) {
                c.x = gelu_tanh(c.x); c.y = gelu_tanh(c.y);
                c.z = gelu_tanh(c.z); c.w = gelu_tanh(c.w);
            }
            if (EPI == 1) {
                const float4 r = *(const float4*)(res + (size_t)m * N + n);
                c.x += r.x; c.y += r.y; c.z += r.z; c.w += r.w;
            }
            *(float4*)(C + (size_t)m * N + n) = c;
        }
    }
}

// ---------------------------------------------------------------------------
// Flash attention (fp32, online softmax). 64 queries x 64 keys per tile,
// hd=64. Grid (L/64, H, B). 256 threads: (ty=tid/16 rows, tx=tid%16 cols),
// each thread owns a 4x4 patch. Reads q/k/v directly out of g_qkv.
// ---------------------------------------------------------------------------
#define FA_STRIDE 68
#define FA_BUF (64 * FA_STRIDE)
#define FA_SMEM (4 * FA_BUF * 4)

__global__ __launch_bounds__(256) void flash_attn_k(
    const float* __restrict__ qkv, float* __restrict__ out)
{
    extern __shared__ float sm[];
    float* Qt = sm;               // [d][m] d-major, stride 68
    float* Kt = Qt + FA_BUF;      // [d][n]
    float* Vs = Kt + FA_BUF;      // [n][d]
    float* Ps = Vs + FA_BUF;      // [m][n]

    const int b = blockIdx.z;
    const int h = blockIdx.y;
    const int qb = blockIdx.x * 64;
    const int t = threadIdx.x;
    const int tm = t >> 4;        // 0..15
    const int tn = t & 15;        // 0..15

    // load Q tile (transposed into Qt[d][m])
    for (int idx = t; idx < 64 * 16; idx += 256) {
        const int m = idx >> 4;
        const int d4 = (idx & 15) * 4;
        const float4 v = *(const float4*)(
            qkv + (size_t)(b * L_ + qb + m) * (3 * D_) + h * HD_ + d4);
        Qt[(d4 + 0) * FA_STRIDE + m] = v.x;
        Qt[(d4 + 1) * FA_STRIDE + m] = v.y;
        Qt[(d4 + 2) * FA_STRIDE + m] = v.z;
        Qt[(d4 + 3) * FA_STRIDE + m] = v.w;
    }

    float mo[4] = {-INFINITY, -INFINITY, -INFINITY, -INFINITY};
    float lo[4] = {0.f, 0.f, 0.f, 0.f};
    float acc[4][4];
    #pragma unroll
    for (int i = 0; i < 4; i++)
        #pragma unroll
        for (int j = 0; j < 4; j++) acc[i][j] = 0.f;

    __syncthreads();

    for (int kb = 0; kb < L_; kb += 64) {
        // load K (transposed) and V tiles
        for (int idx = t; idx < 64 * 16; idx += 256) {
            const int n = idx >> 4;
            const int d4 = (idx & 15) * 4;
            const float* kp = qkv + (size_t)(b * L_ + kb + n) * (3 * D_)
                              + D_ + h * HD_ + d4;
            const float4 kv = *(const float4*)kp;
            Kt[(d4 + 0) * FA_STRIDE + n] = kv.x;
            Kt[(d4 + 1) * FA_STRIDE + n] = kv.y;
            Kt[(d4 + 2) * FA_STRIDE + n] = kv.z;
            Kt[(d4 + 3) * FA_STRIDE + n] = kv.w;
            *(float4*)&Vs[n * FA_STRIDE + d4] = *(const float4*)(kp + D_);
        }
        __syncthreads();

        // S = Q K^T * 0.125
        float s[4][4];
        #pragma unroll
        for (int i = 0; i < 4; i++)
            #pragma unroll
            for (int j = 0; j < 4; j++) s[i][j] = 0.f;
        #pragma unroll 4
        for (int k = 0; k < HD_; k++) {
            const float4 q4 = *(const float4*)&Qt[k * FA_STRIDE + tm * 4];
            const float4 k4 = *(const float4*)&Kt[k * FA_STRIDE + tn * 4];
            const float qr[4] = {q4.x, q4.y, q4.z, q4.w};
            const float kr[4] = {k4.x, k4.y, k4.z, k4.w};
            #pragma unroll
            for (int i = 0; i < 4; i++)
                #pragma unroll
                for (int j = 0; j < 4; j++)
                    s[i][j] = fmaf(qr[i], kr[j], s[i][j]);
        }

        // online softmax per row (16-lane reduction across tn; tn occupies
        // the low 4 lane bits so xor 1/2/4/8 stays within the row group)
        #pragma unroll
        for (int i = 0; i < 4; i++) {
            float tmax = -INFINITY;
            #pragma unroll
            for (int j = 0; j < 4; j++) {
                s[i][j] *= 0.125f;
                tmax = fmaxf(tmax, s[i][j]);
            }
            #pragma unroll
            for (int off = 8; off > 0; off >>= 1)
                tmax = fmaxf(tmax, __shfl_xor_sync(0xffffffffu, tmax, off));

            const float mnew = fmaxf(mo[i], tmax);
            const float corr = __expf(mo[i] - mnew);
            float rs = 0.f;
            #pragma unroll
            for (int j = 0; j < 4; j++) {
                const float p = __expf(s[i][j] - mnew);
                Ps[(tm * 4 + i) * FA_STRIDE + tn * 4 + j] = p;
                rs += p;
            }
            #pragma unroll
            for (int off = 8; off > 0; off >>= 1)
                rs += __shfl_xor_sync(0xffffffffu, rs, off);

            lo[i] = lo[i] * corr + rs;
            mo[i] = mnew;
            #pragma unroll
            for (int j = 0; j < 4; j++) acc[i][j] *= corr;
        }
        __syncthreads();

        // acc += P @ V
        #pragma unroll 4
        for (int kk = 0; kk < 64; kk++) {
            const float4 v4 = *(const float4*)&Vs[kk * FA_STRIDE + tn * 4];
            const float vr[4] = {v4.x, v4.y, v4.z, v4.w};
            #pragma unroll
            for (int i = 0; i < 4; i++) {
                const float p = Ps[(tm * 4 + i) * FA_STRIDE + kk];
                #pragma unroll
                for (int j = 0; j < 4; j++)
                    acc[i][j] = fmaf(p, vr[j], acc[i][j]);
            }
        }
        __syncthreads();
    }

    // write normalized output: out[b][l][h*64+d]
    #pragma unroll
    for (int i = 0; i < 4; i++) {
        const float inv = 1.0f / lo[i];
        float4 o = make_float4(acc[i][0] * inv, acc[i][1] * inv,
                               acc[i][2] * inv, acc[i][3] * inv);
        *(float4*)(out + (size_t)(b * L_ + qb + tm * 4 + i) * D_
                   + h * HD_ + tn * 4) = o;
    }
}

// ---------------------------------------------------------------------------
// Launch
// ---------------------------------------------------------------------------
extern "C" void kernel_launch(void* const* d_in, const int* in_sizes, int n_in,
                              void* d_out, int out_size)
{
    const float* x      = (const float*)d_in[0];
    const float* ln1_s  = (const float*)d_in[1];
    const float* ln1_b  = (const float*)d_in[2];
    const float* w_qkv  = (const float*)d_in[3];
    const float* w_proj = (const float*)d_in[4];
    const float* b_proj = (const float*)d_in[5];
    const float* ln2_s  = (const float*)d_in[6];
    const float* ln2_b  = (const float*)d_in[7];
    const float* w_mlp1 = (const float*)d_in[8];
    const float* b_mlp1 = (const float*)d_in[9];
    const float* w_mlp2 = (const float*)d_in[10];
    const float* b_mlp2 = (const float*)d_in[11];
    float* out = (float*)d_out;

    float *h, *qkv, *attn, *x1, *mid;
    cudaGetSymbolAddress((void**)&h, g_h);
    cudaGetSymbolAddress((void**)&qkv, g_qkv);
    cudaGetSymbolAddress((void**)&attn, g_attn);
    cudaGetSymbolAddress((void**)&x1, g_x1);
    cudaGetSymbolAddress((void**)&mid, g_mid);

    static bool attr_set = false;
    if (!attr_set) {
        cudaFuncSetAttribute(flash_attn_k,
                             cudaFuncAttributeMaxDynamicSharedMemorySize,
                             FA_SMEM);
        attr_set = true;
    }

    // 1) pre-norm 1
    layernorm_k<<<M_, 256>>>(x, ln1_s, ln1_b, h);
    // 2) qkv projection (no bias)
    sgemm128<0><<<dim3(3 * D_ / 128, M_ / 128), 256>>>(
        h, w_qkv, nullptr, nullptr, qkv, M_, 3 * D_, D_);
    // 3) attention
    flash_attn_k<<<dim3(L_ / 64, H_, B_), 256, FA_SMEM>>>(qkv, attn);
    // 4) output projection + bias + residual
    sgemm128<1><<<dim3(D_ / 128, M_ / 128), 256>>>(
        attn, w_proj, b_proj, x, x1, M_, D_, D_);
    // 5) pre-norm 2
    layernorm_k<<<M_, 256>>>(x1, ln2_s, ln2_b, h);
    // 6) MLP up + bias + gelu
    sgemm128<2><<<dim3(F_ / 128, M_ / 128), 256>>>(
        h, w_mlp1, b_mlp1, nullptr, mid, M_, F_, D_);
    // 7) MLP down + bias + residual -> final output
    sgemm128<1><<<dim3(D_ / 128, M_ / 128), 256>>>(
        mid, w_mlp2, b_mlp2, x1, out, M_, D_, F_);
}

// round 5
// speedup vs baseline: 1.0016x; 1.0013x over previous
#include <cuda_runtime.h>
#include <cuda_bf16.h>
#include <math.h>

// Problem constants
#define B_ 2
#define L_ 2048
#define D_ 1024
#define F_ 4096
#define H_ 16
#define HD_ 64
#define M_ (B_ * L_)          // 4096 rows of tokens
#define LN_EPS 1e-6f

// ---------------------------------------------------------------------------
// Scratch (static device globals; no allocation anywhere)
// ---------------------------------------------------------------------------
__device__ float g_h[M_ * D_];        // layernorm output (reused for ln1 and ln2)
__device__ float g_qkv[M_ * 3 * D_];  // qkv projection
__device__ float g_attn[M_ * D_];     // attention output (pre-proj)
__device__ float g_x1[M_ * D_];       // residual stream after attention
__device__ float g_mid[M_ * F_];      // MLP hidden

// ---------------------------------------------------------------------------
// LayerNorm: one block per row (D=1024, 256 threads -> one float4 per thread)
// ---------------------------------------------------------------------------
__global__ __launch_bounds__(256) void layernorm_k(
    const float* __restrict__ x, const float* __restrict__ gamma,
    const float* __restrict__ beta, float* __restrict__ out)
{
    const int row = blockIdx.x;
    const int t = threadIdx.x;
    const float4 v = *(const float4*)(x + (size_t)row * D_ + t * 4);

    float s = v.x + v.y + v.z + v.w;
    float q = v.x * v.x + v.y * v.y + v.z * v.z + v.w * v.w;

    #pragma unroll
    for (int off = 16; off > 0; off >>= 1) {
        s += __shfl_down_sync(0xffffffffu, s, off);
        q += __shfl_down_sync(0xffffffffu, q, off);
    }
    __shared__ float ss[8], qq[8];
    const int wid = t >> 5, lane = t & 31;
    if (lane == 0) { ss[wid] = s; qq[wid] = q; }
    __syncthreads();
    if (t == 0) {
        float S = 0.f, Q = 0.f;
        #pragma unroll
        for (int i = 0; i < 8; i++) { S += ss[i]; Q += qq[i]; }
        ss[0] = S; qq[0] = Q;
    }
    __syncthreads();
    const float mu = ss[0] * (1.0f / D_);
    const float var = qq[0] * (1.0f / D_) - mu * mu;
    const float rstd = rsqrtf(var + LN_EPS);

    const float4 g4 = *(const float4*)(gamma + t * 4);
    const float4 b4 = *(const float4*)(beta + t * 4);
    float4 o;
    o.x = (v.x - mu) * rstd * g4.x + b4.x;
    o.y = (v.y - mu) * rstd * g4.y + b4.y;
    o.z = (v.z - mu) * rstd * g4.z + b4.z;
    o.w = (v.w - mu) * rstd * g4.w + b4.w;
    *(float4*)(out + (size_t)row * D_ + t * 4) = o;
}

// ---------------------------------------------------------------------------
// SGEMM: C[M,N] = A[M,K] @ B[K,N] (+ bias) (+ gelu) (+ residual)
// 128x128 tile, BK=8, 256 threads, 8x8 per thread.
// EPI: 0 = none, 1 = bias + residual, 2 = bias + gelu
// ---------------------------------------------------------------------------
__device__ __forceinline__ float gelu_tanh(float v) {
    const float c = 0.7978845608028654f;
    float u = c * (v + 0.044715f * v * v * v);
    return 0.5f * v * (1.0f + tanhf(u));
}

template <int EPI>
__global__ __launch_bounds__(256) void sgemm128(
    const float* __restrict__ A, const float* __restrict__ Bm,
    const float* __restrict__ bias, const float* __restrict__ res,
    float* __restrict__ C, int M, int N, int K)
{
    __shared__ float As[8][128];
    __shared__ float Bs[8][128];

    const int tid = threadIdx.x;
    const int mBase = blockIdx.y * 128;
    const int nBase = blockIdx.x * 128;

    const int aRow = tid >> 1;          // 0..127
    const int aCol = (tid & 1) * 4;     // 0 or 4
    const int bRow = tid >> 5;          // 0..7
    const int bCol = (tid & 31) * 4;    // 0..124

    const float* Aptr = A + (size_t)(mBase + aRow) * K + aCol;
    const float* Bptr = Bm + (size_t)bRow * N + nBase + bCol;

    const int tx = tid & 15;            // 0..15 -> N sub-tile
    const int ty = tid >> 4;            // 0..15 -> M sub-tile

    float acc[8][8];
    #pragma unroll
    for (int i = 0; i < 8; i++)
        #pragma unroll
        for (int j = 0; j < 8; j++) acc[i][j] = 0.f;

    for (int k0 = 0; k0 < K; k0 += 8) {
        const float4 a4 = *(const float4*)(Aptr + k0);
        const float4 b4 = *(const float4*)(Bptr + (size_t)k0 * N);
        As[aCol + 0][aRow] = a4.x;
        As[aCol + 1][aRow] = a4.y;
        As[aCol + 2][aRow] = a4.z;
        As[aCol + 3][aRow] = a4.w;
        *(float4*)&Bs[bRow][bCol] = b4;
        __syncthreads();

        #pragma unroll
        for (int k = 0; k < 8; k++) {
            const float4 a0 = *(const float4*)&As[k][ty * 8];
            const float4 a1 = *(const float4*)&As[k][ty * 8 + 4];
            const float4 b0 = *(const float4*)&Bs[k][tx * 8];
            const float4 b1 = *(const float4*)&Bs[k][tx * 8 + 4];
            const float ar[8] = {a0.x, a0.y, a0.z, a0.w, a1.x, a1.y, a1.z, a1.w};
            const float br[8] = {b0.x, b0.y, b0.z, b0.w, b1.x, b1.y, b1.z, b1.w};
            #pragma unroll
            for (int i = 0; i < 8; i++)
                #pragma unroll
                for (int j = 0; j < 8; j++)
                    acc[i][j] = fmaf(ar[i], br[j], acc[i][j]);
        }
        __syncthreads();
    }

    // Epilogue
    #pragma unroll
    for (int i = 0; i < 8; i++) {
        const int m = mBase + ty * 8 + i;
        #pragma unroll
        for (int jj = 0; jj < 8; jj += 4) {
            const int n = nBase + tx * 8 + jj;
            float4 c = make_float4(acc[i][jj], acc[i][jj + 1],
                                   acc[i][jj + 2], acc[i][jj + 3]);
            if (EPI == 1 || EPI == 2) {
                const float4 bi = *(const float4*)(bias + n);
                c.x += bi.x; c.y += bi.y; c.z += bi.z; c.w += bi.w;
            }
            if (EPI == 2) {
                c.x = gelu_tanh(c.x); c.y = gelu_tanh(c.y);
                c.z = gelu_tanh(c.z); c.w = gelu_tanh(c.w);
            }
            if (EPI == 1) {
                const float4 r = *(const float4*)(res + (size_t)m * N + n);
                c.x += r.x; c.y += r.y; c.z += r.z; c.w += r.w;
            }
            *(float4*)(C + (size_t)m * N + n) = c;
        }
    }
}

// ---------------------------------------------------------------------------
// Flash attention (fp32, online softmax). 64 queries x 64 keys per tile,
// hd=64. Grid (L/64, H, B). 256 threads: (ty=tid/16 rows, tx=tid%16 cols),
// each thread owns a 4x4 patch. Reads q/k/v directly out of g_qkv.
// ---------------------------------------------------------------------------
#define FA_STRIDE 68
#define FA_BUF (64 * FA_STRIDE)
#define FA_SMEM (4 * FA_BUF * 4)

__global__ __launch_bounds__(256) void flash_attn_k(
    const float* __restrict__ qkv, float* __restrict__ out)
{
    extern __shared__ float sm[];
    float* Qt = sm;               // [d][m] d-major, stride 68
    float* Kt = Qt + FA_BUF;      // [d][n]
    float* Vs = Kt + FA_BUF;      // [n][d]
    float* Ps = Vs + FA_BUF;      // [m][n]

    const int b = blockIdx.z;
    const int h = blockIdx.y;
    const int qb = blockIdx.x * 64;
    const int t = threadIdx.x;
    const int tm = t >> 4;        // 0..15
    const int tn = t & 15;        // 0..15

    // load Q tile (transposed into Qt[d][m])
    for (int idx = t; idx < 64 * 16; idx += 256) {
        const int m = idx >> 4;
        const int d4 = (idx & 15) * 4;
        const float4 v = *(const float4*)(
            qkv + (size_t)(b * L_ + qb + m) * (3 * D_) + h * HD_ + d4);
        Qt[(d4 + 0) * FA_STRIDE + m] = v.x;
        Qt[(d4 + 1) * FA_STRIDE + m] = v.y;
        Qt[(d4 + 2) * FA_STRIDE + m] = v.z;
        Qt[(d4 + 3) * FA_STRIDE + m] = v.w;
    }

    float mo[4] = {-INFINITY, -INFINITY, -INFINITY, -INFINITY};
    float lo[4] = {0.f, 0.f, 0.f, 0.f};
    float acc[4][4];
    #pragma unroll
    for (int i = 0; i < 4; i++)
        #pragma unroll
        for (int j = 0; j < 4; j++) acc[i][j] = 0.f;

    __syncthreads();

    for (int kb = 0; kb < L_; kb += 64) {
        // load K (transposed) and V tiles
        for (int idx = t; idx < 64 * 16; idx += 256) {
            const int n = idx >> 4;
            const int d4 = (idx & 15) * 4;
            const float* kp = qkv + (size_t)(b * L_ + kb + n) * (3 * D_)
                              + D_ + h * HD_ + d4;
            const float4 kv = *(const float4*)kp;
            Kt[(d4 + 0) * FA_STRIDE + n] = kv.x;
            Kt[(d4 + 1) * FA_STRIDE + n] = kv.y;
            Kt[(d4 + 2) * FA_STRIDE + n] = kv.z;
            Kt[(d4 + 3) * FA_STRIDE + n] = kv.w;
            *(float4*)&Vs[n * FA_STRIDE + d4] = *(const float4*)(kp + D_);
        }
        __syncthreads();

        // S = Q K^T * 0.125
        float s[4][4];
        #pragma unroll
        for (int i = 0; i < 4; i++)
            #pragma unroll
            for (int j = 0; j < 4; j++) s[i][j] = 0.f;
        #pragma unroll 4
        for (int k = 0; k < HD_; k++) {
            const float4 q4 = *(const float4*)&Qt[k * FA_STRIDE + tm * 4];
            const float4 k4 = *(const float4*)&Kt[k * FA_STRIDE + tn * 4];
            const float qr[4] = {q4.x, q4.y, q4.z, q4.w};
            const float kr[4] = {k4.x, k4.y, k4.z, k4.w};
            #pragma unroll
            for (int i = 0; i < 4; i++)
                #pragma unroll
                for (int j = 0; j < 4; j++)
                    s[i][j] = fmaf(qr[i], kr[j], s[i][j]);
        }

        // online softmax per row (16-lane reduction across tn; tn occupies
        // the low 4 lane bits so xor 1/2/4/8 stays within the row group)
        #pragma unroll
        for (int i = 0; i < 4; i++) {
            float tmax = -INFINITY;
            #pragma unroll
            for (int j = 0; j < 4; j++) {
                s[i][j] *= 0.125f;
                tmax = fmaxf(tmax, s[i][j]);
            }
            #pragma unroll
            for (int off = 8; off > 0; off >>= 1)
                tmax = fmaxf(tmax, __shfl_xor_sync(0xffffffffu, tmax, off));

            const float mnew = fmaxf(mo[i], tmax);
            const float corr = __expf(mo[i] - mnew);
            float rs = 0.f;
            #pragma unroll
            for (int j = 0; j < 4; j++) {
                const float p = __expf(s[i][j] - mnew);
                Ps[(tm * 4 + i) * FA_STRIDE + tn * 4 + j] = p;
                rs += p;
            }
            #pragma unroll
            for (int off = 8; off > 0; off >>= 1)
                rs += __shfl_xor_sync(0xffffffffu, rs, off);

            lo[i] = lo[i] * corr + rs;
            mo[i] = mnew;
            #pragma unroll
            for (int j = 0; j < 4; j++) acc[i][j] *= corr;
        }
        __syncthreads();

        // acc += P @ V
        #pragma unroll 4
        for (int kk = 0; kk < 64; kk++) {
            const float4 v4 = *(const float4*)&Vs[kk * FA_STRIDE + tn * 4];
            const float vr[4] = {v4.x, v4.y, v4.z, v4.w};
            #pragma unroll
            for (int i = 0; i < 4; i++) {
                const float p = Ps[(tm * 4 + i) * FA_STRIDE + kk];
                #pragma unroll
                for (int j = 0; j < 4; j++)
                    acc[i][j] = fmaf(p, vr[j], acc[i][j]);
            }
        }
        __syncthreads();
    }

    // write normalized output: out[b][l][h*64+d]
    #pragma unroll
    for (int i = 0; i < 4; i++) {
        const float inv = 1.0f / lo[i];
        float4 o = make_float4(acc[i][0] * inv, acc[i][1] * inv,
                               acc[i][2] * inv, acc[i][3] * inv);
        *(float4*)(out + (size_t)(b * L_ + qb + tm * 4 + i) * D_
                   + h * HD_ + tn * 4) = o;
    }
}

// ---------------------------------------------------------------------------
// Launch
// ---------------------------------------------------------------------------
extern "C" void kernel_launch(void* const* d_in, const int* in_sizes, int n_in,
                              void* d_out, int out_size)
{
    const float* x      = (const float*)d_in[0];
    const float* ln1_s  = (const float*)d_in[1];
    const float* ln1_b  = (const float*)d_in[2];
    const float* w_qkv  = (const float*)d_in[3];
    const float* w_proj = (const float*)d_in[4];
    const float* b_proj = (const float*)d_in[5];
    const float* ln2_s  = (const float*)d_in[6];
    const float* ln2_b  = (const float*)d_in[7];
    const float* w_mlp1 = (const float*)d_in[8];
    const float* b_mlp1 = (const float*)d_in[9];
    const float* w_mlp2 = (const float*)d_in[10];
    const float* b_mlp2 = (const float*)d_in[11];
    float* out = (float*)d_out;

    float *h, *qkv, *attn, *x1, *mid;
    cudaGetSymbolAddress((void**)&h, g_h);
    cudaGetSymbolAddress((void**)&qkv, g_qkv);
    cudaGetSymbolAddress((void**)&attn, g_attn);
    cudaGetSymbolAddress((void**)&x1, g_x1);
    cudaGetSymbolAddress((void**)&mid, g_mid);

    static bool attr_set = false;
    if (!attr_set) {
        cudaFuncSetAttribute(flash_attn_k,
                             cudaFuncAttributeMaxDynamicSharedMemorySize,
                             FA_SMEM);
        attr_set = true;
    }

    // 1) pre-norm 1
    layernorm_k<<<M_, 256>>>(x, ln1_s, ln1_b, h);
    // 2) qkv projection (no bias)
    sgemm128<0><<<dim3(3 * D_ / 128, M_ / 128), 256>>>(
        h, w_qkv, nullptr, nullptr, qkv, M_, 3 * D_, D_);
    // 3) attention
    flash_attn_k<<<dim3(L_ / 64, H_, B_), 256, FA_SMEM>>>(qkv, attn);
    // 4) output projection + bias + residual
    sgemm128<1><<<dim3(D_ / 128, M_ / 128), 256>>>(
        attn, w_proj, b_proj, x, x1, M_, D_, D_);
    // 5) pre-norm 2
    layernorm_k<<<M_, 256>>>(x1, ln2_s, ln2_b, h);
    // 6) MLP up + bias + gelu
    sgemm128<2><<<dim3(F_ / 128, M_ / 128), 256>>>(
        h, w_mlp1, b_mlp1, nullptr, mid, M_, F_, D_);
    // 7) MLP down + bias + residual -> final output
    sgemm128<1><<<dim3(D_ / 128, M_ / 128), 256>>>(
        mid, w_mlp2, b_mlp2, x1, out, M_, D_, F_);
}